// round 3
// baseline (speedup 1.0000x reference)
#include <cuda_runtime.h>
#include <cstdint>

// HDConvEncoder: 8-step depthwise-conv3 recurrence + LayerNorm(L) + pw scale/bias
// + exact GELU + residual. B=32, C=256, L=4096, S=8, Cs=32.
// One block per (b, c_local) chain (1024 blocks). y-state and z live in registers;
// conv neighbors via warp shuffles + per-warp SMEM edge scalars. x prefetched
// register-free via cp.async into a double-buffered SMEM staging area.

#define NT 512
#define LLEN 4096
#define NG 8
#define CS 32
#define CTOT 256

__device__ __forceinline__ uint32_t smem_u32(const void* p) {
    return (uint32_t)__cvta_generic_to_shared(p);
}

__device__ __forceinline__ float gelu_exact(float t) {
    return 0.5f * t * (1.0f + erff(t * 0.70710678118654752440f));
}

__global__ void __launch_bounds__(NT, 3)
hdconv_encoder_kernel(const float* __restrict__ x,
                      const float* __restrict__ conv_w,   // [8,3,32]
                      const float* __restrict__ conv_b,   // [8,32]
                      const float* __restrict__ ln_g,     // [4096]
                      const float* __restrict__ ln_b,     // [4096]
                      const float* __restrict__ pw_w,     // [256]
                      const float* __restrict__ pw_b,     // [256]
                      float* __restrict__ out)
{
    extern __shared__ float sm[];
    float* sgam = sm;                  // 4096
    float* sbet = sm + LLEN;           // 4096
    float* xb0  = sm + 2 * LLEN;       // 4096 (x stage buf 0)
    float* xb1  = sm + 3 * LLEN;       // 4096 (x stage buf 1)
    float* eA   = sm + 4 * LLEN;       // 32: first z of each warp-chunk
    float* eB   = eA + 32;             // 32: last  z of each warp-chunk
    float* red  = eB + 32;             // 32: (s,ss) partials per warp

    const int tid  = threadIdx.x;
    const int lane = tid & 31;
    const int warp = tid >> 5;
    const int b    = blockIdx.x >> 5;
    const int cl   = blockIdx.x & 31;

    const float* xbase = x   + ((long)b * CTOT + cl) * LLEN;
    float*       obase = out + ((long)b * CTOT + cl) * LLEN;

    // gamma/beta -> SMEM. Each thread writes and later reads ONLY its own slots
    // (q = tid, tid+NT), so no barrier is needed for these.
    {
        const float4* g4 = (const float4*)ln_g;
        const float4* b4 = (const float4*)ln_b;
        ((float4*)sgam)[tid]      = g4[tid];
        ((float4*)sgam)[tid + NT] = g4[tid + NT];
        ((float4*)sbet)[tid]      = b4[tid];
        ((float4*)sbet)[tid + NT] = b4[tid + NT];
    }

    // Register-free prefetch: LDGSTS 16B x2 per thread into own SMEM slots.
    auto prefetch = [&](int i, float* buf) {
        const float* src = xbase + (long)i * CS * LLEN;
        uint32_t d0 = smem_u32(buf + 4 * tid);
        uint32_t d1 = smem_u32(buf + 4 * (tid + NT));
        asm volatile("cp.async.cg.shared.global [%0], [%1], 16;\n" :: "r"(d0), "l"(src + 4 * tid));
        asm volatile("cp.async.cg.shared.global [%0], [%1], 16;\n" :: "r"(d1), "l"(src + 4 * (tid + NT)));
        asm volatile("cp.async.commit_group;\n");
    };
    prefetch(0, xb0);

    float4 yv0 = make_float4(0.f, 0.f, 0.f, 0.f);
    float4 yv1 = make_float4(0.f, 0.f, 0.f, 0.f);

    const int wq0 = tid >> 5;          // warp-chunk id for q = tid       (0..15)
    const int wq1 = (tid + NT) >> 5;   // warp-chunk id for q = tid + NT  (16..31)

#pragma unroll 1
    for (int i = 0; i < NG; i++) {
        float* curb = (i & 1) ? xb1 : xb0;
        float* nxtb = (i & 1) ? xb0 : xb1;
        if (i < NG - 1) {
            prefetch(i + 1, nxtb);
            asm volatile("cp.async.wait_group 1;\n");
        } else {
            asm volatile("cp.async.wait_group 0;\n");
        }

        // x for this group (own slots; data landed per wait_group above).
        float4 xv0 = ((const float4*)curb)[tid];
        float4 xv1 = ((const float4*)curb)[tid + NT];

        // Per-group scalars (broadcast, L2-resident).
        const float w0  = __ldg(conv_w + i * 96 + 0 * 32 + cl);
        const float w1  = __ldg(conv_w + i * 96 + 1 * 32 + cl);
        const float w2  = __ldg(conv_w + i * 96 + 2 * 32 + cl);
        const float bb  = __ldg(conv_b + i * 32 + cl);
        const float pww = __ldg(pw_w + i * 32 + cl);
        const float pwb = __ldg(pw_b + i * 32 + cl);

        // z = x + y_prev, in place (yv becomes z).
        yv0.x += xv0.x; yv0.y += xv0.y; yv0.z += xv0.z; yv0.w += xv0.w;
        yv1.x += xv1.x; yv1.y += xv1.y; yv1.z += xv1.z; yv1.w += xv1.w;

        // Warp-chunk edge values for cross-warp conv taps.
        if (lane == 0)  { eA[wq0] = yv0.x; eA[wq1] = yv1.x; }
        if (lane == 31) { eB[wq0] = yv0.w; eB[wq1] = yv1.w; }
        __syncthreads();

        float s = 0.f, ss = 0.f;

        // conv3, block j=0 (elements 4*tid .. 4*tid+3)
        {
            float zmw = __shfl_up_sync(0xFFFFFFFFu, yv0.w, 1);
            float zpx = __shfl_down_sync(0xFFFFFFFFu, yv0.x, 1);
            float zm = (lane == 0)  ? ((wq0 == 0)  ? 0.f : eB[wq0 - 1]) : zmw;
            float zp = (lane == 31) ? ((wq0 == 31) ? 0.f : eA[wq0 + 1]) : zpx;
            float4 zc = yv0, yo;
            yo.x = fmaf(w0, zm,   fmaf(w1, zc.x, fmaf(w2, zc.y, bb)));
            yo.y = fmaf(w0, zc.x, fmaf(w1, zc.y, fmaf(w2, zc.z, bb)));
            yo.z = fmaf(w0, zc.y, fmaf(w1, zc.z, fmaf(w2, zc.w, bb)));
            yo.w = fmaf(w0, zc.z, fmaf(w1, zc.w, fmaf(w2, zp,   bb)));
            s  += yo.x + yo.y + yo.z + yo.w;
            ss += yo.x * yo.x + yo.y * yo.y + yo.z * yo.z + yo.w * yo.w;
            yv0 = yo;
        }
        // conv3, block j=1 (elements 4*(tid+NT) .. +3)
        {
            float zmw = __shfl_up_sync(0xFFFFFFFFu, yv1.w, 1);
            float zpx = __shfl_down_sync(0xFFFFFFFFu, yv1.x, 1);
            float zm = (lane == 0)  ? ((wq1 == 0)  ? 0.f : eB[wq1 - 1]) : zmw;
            float zp = (lane == 31) ? ((wq1 == 31) ? 0.f : eA[wq1 + 1]) : zpx;
            float4 zc = yv1, yo;
            yo.x = fmaf(w0, zm,   fmaf(w1, zc.x, fmaf(w2, zc.y, bb)));
            yo.y = fmaf(w0, zc.x, fmaf(w1, zc.y, fmaf(w2, zc.z, bb)));
            yo.z = fmaf(w0, zc.y, fmaf(w1, zc.z, fmaf(w2, zc.w, bb)));
            yo.w = fmaf(w0, zc.z, fmaf(w1, zc.w, fmaf(w2, zp,   bb)));
            s  += yo.x + yo.y + yo.z + yo.w;
            ss += yo.x * yo.x + yo.y * yo.y + yo.z * yo.z + yo.w * yo.w;
            yv1 = yo;
        }

        // Block reduction: warp shfl reduce -> SMEM partials -> every warp
        // redundantly reduces all 16 partials (no broadcast barrier needed).
#pragma unroll
        for (int o = 16; o > 0; o >>= 1) {
            s  += __shfl_xor_sync(0xFFFFFFFFu, s,  o);
            ss += __shfl_xor_sync(0xFFFFFFFFu, ss, o);
        }
        if (lane == 0) { red[2 * warp] = s; red[2 * warp + 1] = ss; }
        __syncthreads();
        float a = (lane < 16) ? red[2 * lane]     : 0.f;
        float c = (lane < 16) ? red[2 * lane + 1] : 0.f;
#pragma unroll
        for (int o = 8; o > 0; o >>= 1) {
            a += __shfl_xor_sync(0xFFFFFFFFu, a, o);
            c += __shfl_xor_sync(0xFFFFFFFFu, c, o);
        }
        a = __shfl_sync(0xFFFFFFFFu, a, 0);
        c = __shfl_sync(0xFFFFFFFFu, c, 0);

        const float mean = a * (1.0f / (float)LLEN);
        const float rstd = rsqrtf(c * (1.0f / (float)LLEN) - mean * mean + 1e-6f);
        const float c0   = -mean * rstd;

        // LN + pw + exact gelu + residual; streaming stores.
        float* orow = obase + (long)i * CS * LLEN;
        {
            float4 g  = ((const float4*)sgam)[tid];
            float4 be = ((const float4*)sbet)[tid];
            float4 o;
            o.x = xv0.x + gelu_exact(fmaf(fmaf(fmaf(yv0.x, rstd, c0), g.x, be.x), pww, pwb));
            o.y = xv0.y + gelu_exact(fmaf(fmaf(fmaf(yv0.y, rstd, c0), g.y, be.y), pww, pwb));
            o.z = xv0.z + gelu_exact(fmaf(fmaf(fmaf(yv0.z, rstd, c0), g.z, be.z), pww, pwb));
            o.w = xv0.w + gelu_exact(fmaf(fmaf(fmaf(yv0.w, rstd, c0), g.w, be.w), pww, pwb));
            __stcs(((float4*)orow) + tid, o);
        }
        {
            float4 g  = ((const float4*)sgam)[tid + NT];
            float4 be = ((const float4*)sbet)[tid + NT];
            float4 o;
            o.x = xv1.x + gelu_exact(fmaf(fmaf(fmaf(yv1.x, rstd, c0), g.x, be.x), pww, pwb));
            o.y = xv1.y + gelu_exact(fmaf(fmaf(fmaf(yv1.y, rstd, c0), g.y, be.y), pww, pwb));
            o.z = xv1.z + gelu_exact(fmaf(fmaf(fmaf(yv1.z, rstd, c0), g.z, be.z), pww, pwb));
            o.w = xv1.w + gelu_exact(fmaf(fmaf(fmaf(yv1.w, rstd, c0), g.w, be.w), pww, pwb));
            __stcs(((float4*)orow) + tid + NT, o);
        }
    }
}

extern "C" void kernel_launch(void* const* d_in, const int* in_sizes, int n_in,
                              void* d_out, int out_size)
{
    const float* x      = (const float*)d_in[0];
    const float* conv_w = (const float*)d_in[1];
    const float* conv_b = (const float*)d_in[2];
    const float* ln_g   = (const float*)d_in[3];
    const float* ln_b   = (const float*)d_in[4];
    const float* pw_w   = (const float*)d_in[5];
    const float* pw_b   = (const float*)d_in[6];
    float* out = (float*)d_out;

    const int smem_bytes = (4 * LLEN + 96) * (int)sizeof(float); // 65920
    cudaFuncSetAttribute(hdconv_encoder_kernel,
                         cudaFuncAttributeMaxDynamicSharedMemorySize, smem_bytes);

    dim3 grid(32 * 32); // B * Cs = 1024 chains
    dim3 block(NT);
    hdconv_encoder_kernel<<<grid, block, smem_bytes>>>(
        x, conv_w, conv_b, ln_g, ln_b, pw_w, pw_b, out);
}

// round 4
// speedup vs baseline: 1.0807x; 1.0807x over previous
#include <cuda_runtime.h>
#include <cstdint>

// HDConvEncoder: 8-step depthwise-conv3 recurrence + LayerNorm(L) + pw scale/bias
// + exact-grade GELU + residual. B=32, C=256, L=4096, S=8, Cs=32.
// One block per (b, c_local) chain (1024 blocks). Issue-bound -> all elementwise
// math in packed f32x2 (FFMA2), GELU via branchless A&S-7.1.26 erf (abs err 2.5e-5).

#define NT 512
#define LLEN 4096
#define NG 8
#define CS 32
#define CTOT 256

typedef unsigned long long u64;

__device__ __forceinline__ uint32_t smem_u32(const void* p) {
    return (uint32_t)__cvta_generic_to_shared(p);
}
__device__ __forceinline__ u64 pk2(float lo, float hi) {
    u64 r;
    asm("mov.b64 %0, {%1, %2};" : "=l"(r) : "r"(__float_as_uint(lo)), "r"(__float_as_uint(hi)));
    return r;
}
__device__ __forceinline__ void upk2(u64 p, float& lo, float& hi) {
    uint32_t a, b;
    asm("mov.b64 {%0, %1}, %2;" : "=r"(a), "=r"(b) : "l"(p));
    lo = __uint_as_float(a); hi = __uint_as_float(b);
}
__device__ __forceinline__ u64 splat2(float v) { return pk2(v, v); }
__device__ __forceinline__ u64 fma2(u64 a, u64 b, u64 c) {
    u64 r; asm("fma.rn.f32x2 %0, %1, %2, %3;" : "=l"(r) : "l"(a), "l"(b), "l"(c)); return r;
}
__device__ __forceinline__ u64 mul2(u64 a, u64 b) {
    u64 r; asm("mul.rn.f32x2 %0, %1, %2;" : "=l"(r) : "l"(a), "l"(b)); return r;
}
__device__ __forceinline__ u64 add2(u64 a, u64 b) {
    u64 r; asm("add.rn.f32x2 %0, %1, %2;" : "=l"(r) : "l"(a), "l"(b)); return r;
}
__device__ __forceinline__ u64 abs2(u64 a, u64 mask) {
    u64 r; asm("and.b64 %0, %1, %2;" : "=l"(r) : "l"(a), "l"(mask)); return r;
}
__device__ __forceinline__ float frcp(float x) {
    float r; asm("rcp.approx.f32 %0, %1;" : "=f"(r) : "f"(x)); return r;
}
__device__ __forceinline__ float fex2(float x) {
    float r; asm("ex2.approx.f32 %0, %1;" : "=f"(r) : "f"(x)); return r;
}

__global__ void __launch_bounds__(NT, 2)
hdconv_encoder_kernel(const float* __restrict__ x,
                      const float* __restrict__ conv_w,   // [8,3,32]
                      const float* __restrict__ conv_b,   // [8,32]
                      const float* __restrict__ ln_g,     // [4096]
                      const float* __restrict__ ln_b,     // [4096]
                      const float* __restrict__ pw_w,     // [256]
                      const float* __restrict__ pw_b,     // [256]
                      float* __restrict__ out)
{
    extern __shared__ float sm[];
    float* sgam = sm;                  // 4096
    float* sbet = sm + LLEN;           // 4096
    float* xb0  = sm + 2 * LLEN;       // 4096 (x stage buf 0)
    float* xb1  = sm + 3 * LLEN;       // 4096 (x stage buf 1)
    float* eA   = sm + 4 * LLEN;       // 32 first-z per warp-chunk
    float* eB   = eA + 32;             // 32 last-z per warp-chunk
    float* red  = eB + 32;             // 32 (s,ss) partials

    const int tid  = threadIdx.x;
    const int lane = tid & 31;
    const int warp = tid >> 5;
    const int b    = blockIdx.x >> 5;
    const int cl   = blockIdx.x & 31;

    const float* xbase = x   + ((long)b * CTOT + cl) * LLEN;
    float*       obase = out + ((long)b * CTOT + cl) * LLEN;

    // gamma/beta -> SMEM (own-slot access only; no barrier needed for these).
    {
        const float4* g4 = (const float4*)ln_g;
        const float4* b4 = (const float4*)ln_b;
        ((float4*)sgam)[tid]      = g4[tid];
        ((float4*)sgam)[tid + NT] = g4[tid + NT];
        ((float4*)sbet)[tid]      = b4[tid];
        ((float4*)sbet)[tid + NT] = b4[tid + NT];
    }

    auto prefetch = [&](int i, float* buf) {
        const float* src = xbase + (long)i * CS * LLEN;
        uint32_t d0 = smem_u32(buf + 4 * tid);
        uint32_t d1 = smem_u32(buf + 4 * (tid + NT));
        asm volatile("cp.async.cg.shared.global [%0], [%1], 16;\n" :: "r"(d0), "l"(src + 4 * tid));
        asm volatile("cp.async.cg.shared.global [%0], [%1], 16;\n" :: "r"(d1), "l"(src + 4 * (tid + NT)));
        asm volatile("cp.async.commit_group;\n");
    };
    prefetch(0, xb0);

    // Packed loop-invariant constants.
    const u64 ABSM  = 0x7FFFFFFF7FFFFFFFull;
    const u64 CP    = splat2(0.33267031f);     // 0.47047 / sqrt(2)
    const u64 CL2   = splat2(-0.72134752f);    // -log2(e)/2
    const u64 CA3   = splat2(-0.7478556f);
    const u64 CA2   = splat2(0.0958798f);
    const u64 CA1   = splat2(-0.3480242f);
    const u64 ONE2  = splat2(1.0f);
    const u64 HALF2 = splat2(0.5f);

    u64 Y[4];
    Y[0] = Y[1] = Y[2] = Y[3] = 0ull; // packed zeros

    const int wq0 = tid >> 5;
    const int wq1 = (tid + NT) >> 5;

#pragma unroll 1
    for (int i = 0; i < NG; i++) {
        float* curb = (i & 1) ? xb1 : xb0;
        float* nxtb = (i & 1) ? xb0 : xb1;
        if (i < NG - 1) {
            prefetch(i + 1, nxtb);
            asm volatile("cp.async.wait_group 1;\n");
        } else {
            asm volatile("cp.async.wait_group 0;\n");
        }

        float4 xa = ((const float4*)curb)[tid];
        float4 xb = ((const float4*)curb)[tid + NT];
        u64 X[4] = { pk2(xa.x, xa.y), pk2(xa.z, xa.w),
                     pk2(xb.x, xb.y), pk2(xb.z, xb.w) };

        const float w0  = __ldg(conv_w + i * 96 + 0 * 32 + cl);
        const float w1  = __ldg(conv_w + i * 96 + 1 * 32 + cl);
        const float w2  = __ldg(conv_w + i * 96 + 2 * 32 + cl);
        const float bb  = __ldg(conv_b + i * 32 + cl);
        const float pww = __ldg(pw_w + i * 32 + cl);
        const float pwb = __ldg(pw_b + i * 32 + cl);

        // z = x + y_prev (packed)
        u64 Z0 = add2(Y[0], X[0]);
        u64 Z1 = add2(Y[1], X[1]);
        u64 Z2 = add2(Y[2], X[2]);
        u64 Z3 = add2(Y[3], X[3]);

        float z0, z1, z2, z3, z4_, z5, z6, z7;
        upk2(Z0, z0, z1); upk2(Z1, z2, z3);
        upk2(Z2, z4_, z5); upk2(Z3, z6, z7);

        if (lane == 0)  { eA[wq0] = z0; eA[wq1] = z4_; }
        if (lane == 31) { eB[wq0] = z3; eB[wq1] = z7; }
        __syncthreads();

        float zmw0 = __shfl_up_sync(0xFFFFFFFFu, z3, 1);
        float zpx0 = __shfl_down_sync(0xFFFFFFFFu, z0, 1);
        float zmw1 = __shfl_up_sync(0xFFFFFFFFu, z7, 1);
        float zpx1 = __shfl_down_sync(0xFFFFFFFFu, z4_, 1);
        float zm0 = (lane == 0)  ? ((wq0 == 0)  ? 0.f : eB[wq0 - 1]) : zmw0;
        float zp0 = (lane == 31) ? ((wq0 == 31) ? 0.f : eA[wq0 + 1]) : zpx0;
        float zm1 = (lane == 0)  ? ((wq1 == 0)  ? 0.f : eB[wq1 - 1]) : zmw1;
        float zp1 = (lane == 31) ? ((wq1 == 31) ? 0.f : eA[wq1 + 1]) : zpx1;

        const u64 W0 = splat2(w0), W1 = splat2(w1), W2 = splat2(w2), BB = splat2(bb);

        // conv3 packed: Y = w0*A + w1*B + w2*C + bb
        {
            u64 C01 = pk2(z1, z2);           // shared (z1,z2)
            u64 t;
            t = fma2(W2, C01, BB); t = fma2(W1, Z0, t); Y[0] = fma2(W0, pk2(zm0, z0), t);
            t = fma2(W2, pk2(z3, zp0), BB); t = fma2(W1, Z1, t); Y[1] = fma2(W0, C01, t);
            u64 C23 = pk2(z5, z6);
            t = fma2(W2, C23, BB); t = fma2(W1, Z2, t); Y[2] = fma2(W0, pk2(zm1, z4_), t);
            t = fma2(W2, pk2(z7, zp1), BB); t = fma2(W1, Z3, t); Y[3] = fma2(W0, C23, t);
        }

        // packed partial sums
        u64 PS  = add2(add2(Y[0], Y[1]), add2(Y[2], Y[3]));
        u64 PSS = fma2(Y[0], Y[0], fma2(Y[1], Y[1], fma2(Y[2], Y[2], mul2(Y[3], Y[3]))));
        float s0, s1, q0, q1;
        upk2(PS, s0, s1); upk2(PSS, q0, q1);
        float s = s0 + s1, ss = q0 + q1;

#pragma unroll
        for (int o = 16; o > 0; o >>= 1) {
            s  += __shfl_xor_sync(0xFFFFFFFFu, s,  o);
            ss += __shfl_xor_sync(0xFFFFFFFFu, ss, o);
        }
        if (lane == 0) { red[2 * warp] = s; red[2 * warp + 1] = ss; }
        __syncthreads();
        float a = (lane < 16) ? red[2 * lane]     : 0.f;
        float c = (lane < 16) ? red[2 * lane + 1] : 0.f;
#pragma unroll
        for (int o = 8; o > 0; o >>= 1) {
            a += __shfl_xor_sync(0xFFFFFFFFu, a, o);
            c += __shfl_xor_sync(0xFFFFFFFFu, c, o);
        }
        a = __shfl_sync(0xFFFFFFFFu, a, 0);
        c = __shfl_sync(0xFFFFFFFFu, c, 0);

        const float mean = a * (1.0f / (float)LLEN);
        const float rstd = rsqrtf(c * (1.0f / (float)LLEN) - mean * mean + 1e-6f);
        const u64 RSTD = splat2(rstd);
        const u64 C0   = splat2(-mean * rstd);
        const u64 PWW  = splat2(pww);
        const u64 PWB  = splat2(pwb);

        float4 ga = ((const float4*)sgam)[tid];
        float4 gb = ((const float4*)sgam)[tid + NT];
        float4 ba = ((const float4*)sbet)[tid];
        float4 bbv = ((const float4*)sbet)[tid + NT];
        u64 G[4]  = { pk2(ga.x, ga.y), pk2(ga.z, ga.w), pk2(gb.x, gb.y), pk2(gb.z, gb.w) };
        u64 Be[4] = { pk2(ba.x, ba.y), pk2(ba.z, ba.w), pk2(bbv.x, bbv.y), pk2(bbv.z, bbv.w) };

        u64 O[4];
#pragma unroll
        for (int j = 0; j < 4; j++) {
            // LN apply + pointwise
            u64 T = fma2(fma2(fma2(Y[j], RSTD, C0), G[j], Be[j]), PWW, PWB);
            // gelu(T) = 0.5*(T + |T| * erf(|T|/sqrt2)), A&S 7.1.26
            u64 U  = abs2(T, ABSM);
            u64 T2 = mul2(T, T);
            u64 EA = mul2(T2, CL2);                 // -x^2 * log2(e), x = T/sqrt2
            u64 D  = fma2(U, CP, ONE2);             // 1 + p*|x|
            float d0, d1, e0, e1;
            upk2(D, d0, d1); upk2(EA, e0, e1);
            u64 K = pk2(frcp(d0), frcp(d1));
            u64 E = pk2(fex2(e0), fex2(e1));
            u64 q = fma2(K, CA3, CA2);
            q = fma2(K, q, CA1);
            u64 P = mul2(K, q);                     // = -(a1 k + a2 k^2 + a3 k^3)
            u64 Gv = fma2(P, E, ONE2);              // erf(|x|)
            u64 R  = fma2(U, Gv, T);                // T + |T|*erf
            O[j] = fma2(HALF2, R, X[j]);            // residual + 0.5*(...)
        }

        float* orow = obase + (long)i * CS * LLEN;
        float4 o0, o1;
        upk2(O[0], o0.x, o0.y); upk2(O[1], o0.z, o0.w);
        upk2(O[2], o1.x, o1.y); upk2(O[3], o1.z, o1.w);
        __stcs(((float4*)orow) + tid,      o0);
        __stcs(((float4*)orow) + tid + NT, o1);
    }
}

extern "C" void kernel_launch(void* const* d_in, const int* in_sizes, int n_in,
                              void* d_out, int out_size)
{
    const float* x      = (const float*)d_in[0];
    const float* conv_w = (const float*)d_in[1];
    const float* conv_b = (const float*)d_in[2];
    const float* ln_g   = (const float*)d_in[3];
    const float* ln_b   = (const float*)d_in[4];
    const float* pw_w   = (const float*)d_in[5];
    const float* pw_b   = (const float*)d_in[6];
    float* out = (float*)d_out;

    const int smem_bytes = (4 * LLEN + 96) * (int)sizeof(float); // 65920
    cudaFuncSetAttribute(hdconv_encoder_kernel,
                         cudaFuncAttributeMaxDynamicSharedMemorySize, smem_bytes);

    dim3 grid(32 * 32);
    dim3 block(NT);
    hdconv_encoder_kernel<<<grid, block, smem_bytes>>>(
        x, conv_w, conv_b, ln_g, ln_b, pw_w, pw_b, out);
}